// round 1
// baseline (speedup 1.0000x reference)
#include <cuda_runtime.h>
#include <math.h>

#define B_   256
#define T_   64
#define H_   1024
#define V_   128
#define L_   32
#define N4H  4096

// ---------------- persistent device scratch (no allocs allowed) ----------------
__device__ float g_h[B_ * H_];
__device__ float g_c[B_ * H_];
__device__ float g_z[B_ * N4H];
__device__ float g_decEW[V_ * N4H];   // dec_emb @ dec_W  (precomputed once)
__device__ int   g_tok[B_];

// ---------------- packed f32x2 helpers (Blackwell FFMA2, PTX-only) ----------------
__device__ __forceinline__ unsigned long long pk2(float lo, float hi) {
    unsigned long long r;
    asm("mov.b64 %0, {%1, %2};" : "=l"(r) : "f"(lo), "f"(hi));
    return r;
}
__device__ __forceinline__ void fma2(unsigned long long& d, unsigned long long a, unsigned long long b) {
    asm("fma.rn.f32x2 %0, %1, %2, %0;" : "+l"(d) : "l"(a), "l"(b));
}
__device__ __forceinline__ float2 unpk2(unsigned long long v) {
    float2 r;
    asm("mov.b64 {%0, %1}, %2;" : "=f"(r.x), "=f"(r.y) : "l"(v));
    return r;
}

// ---------------- fused step GEMM ----------------
// Z[m,n] = (emb ? emb[rows[m]] @ W : 0)
//        + (hIn ? hIn[m] @ U       : 0)
//        + (addTbl ? addTbl[addIdx[m], n] : 0)
//        + (bias ? bias[n] : 0)
// Tile: BM=64, BN=128, BK=16. 256 threads; each thread: 4 rows x 4 col-pairs (f32x2 accum).
#define BM 64
#define BN 128
#define BK 16

__global__ __launch_bounds__(256)
void lstm_gemm(const float* __restrict__ hIn, const float* __restrict__ U,
               const float* __restrict__ emb, const float* __restrict__ W,
               const int* __restrict__ idxPtr, int idxStride,
               const float* __restrict__ addTbl, const int* __restrict__ addIdx,
               const float* __restrict__ bias, float* __restrict__ Z)
{
    __shared__ float As[BK][BM + 1];
    __shared__ float Bs[BK][BN];
    __shared__ int   rows_s[BM];

    const int bn  = blockIdx.x * BN;
    const int bm  = blockIdx.y * BM;
    const int tid = threadIdx.x;
    const int tx  = tid & 15;        // 0..15 -> column pairs
    const int ty  = tid >> 4;        // 0..15 -> row group of 4

    if (tid < BM) {
        int r;
        if (idxPtr)      r = idxPtr[(size_t)(bm + tid) * idxStride];
        else if (addIdx) r = addIdx[bm + tid];
        else             r = bm + tid;
        rows_s[tid] = r;
    }
    __syncthreads();

    unsigned long long acc[4][4];
#pragma unroll
    for (int r = 0; r < 4; r++)
#pragma unroll
        for (int p = 0; p < 4; p++) acc[r][p] = 0ull;

    // ---- source 1: h @ U ----
    if (hIn) {
        for (int k0 = 0; k0 < H_; k0 += BK) {
            {
                int m  = tid >> 2;
                int kq = (tid & 3) << 2;
                float4 v = *(const float4*)(hIn + (size_t)(bm + m) * H_ + k0 + kq);
                As[kq + 0][m] = v.x; As[kq + 1][m] = v.y;
                As[kq + 2][m] = v.z; As[kq + 3][m] = v.w;
            }
            {
                int k  = tid >> 4;
                int n8 = (tid & 15) << 3;
                const float* bp = U + (size_t)(k0 + k) * N4H + bn + n8;
                *(float4*)&Bs[k][n8]     = *(const float4*)bp;
                *(float4*)&Bs[k][n8 + 4] = *(const float4*)(bp + 4);
            }
            __syncthreads();
#pragma unroll
            for (int k = 0; k < BK; k++) {
                unsigned long long a[4], b[4];
#pragma unroll
                for (int r = 0; r < 4; r++) { float av = As[k][ty * 4 + r]; a[r] = pk2(av, av); }
#pragma unroll
                for (int p = 0; p < 4; p++) b[p] = *(const unsigned long long*)&Bs[k][tx * 2 + 32 * p];
#pragma unroll
                for (int r = 0; r < 4; r++)
#pragma unroll
                    for (int p = 0; p < 4; p++) fma2(acc[r][p], a[r], b[p]);
            }
            __syncthreads();
        }
    }

    // ---- source 2: gathered emb @ W ----
    if (emb) {
        for (int k0 = 0; k0 < H_; k0 += BK) {
            {
                int m  = tid >> 2;
                int kq = (tid & 3) << 2;
                const float* ap = emb + (size_t)rows_s[m] * H_ + k0 + kq;
                float4 v = *(const float4*)ap;
                As[kq + 0][m] = v.x; As[kq + 1][m] = v.y;
                As[kq + 2][m] = v.z; As[kq + 3][m] = v.w;
            }
            {
                int k  = tid >> 4;
                int n8 = (tid & 15) << 3;
                const float* bp = W + (size_t)(k0 + k) * N4H + bn + n8;
                *(float4*)&Bs[k][n8]     = *(const float4*)bp;
                *(float4*)&Bs[k][n8 + 4] = *(const float4*)(bp + 4);
            }
            __syncthreads();
#pragma unroll
            for (int k = 0; k < BK; k++) {
                unsigned long long a[4], b[4];
#pragma unroll
                for (int r = 0; r < 4; r++) { float av = As[k][ty * 4 + r]; a[r] = pk2(av, av); }
#pragma unroll
                for (int p = 0; p < 4; p++) b[p] = *(const unsigned long long*)&Bs[k][tx * 2 + 32 * p];
#pragma unroll
                for (int r = 0; r < 4; r++)
#pragma unroll
                    for (int p = 0; p < 4; p++) fma2(acc[r][p], a[r], b[p]);
            }
            __syncthreads();
        }
    }

    // ---- epilogue ----
#pragma unroll
    for (int r = 0; r < 4; r++) {
        int m = bm + ty * 4 + r;
        const float* arow = addTbl ? (addTbl + (size_t)rows_s[ty * 4 + r] * N4H) : nullptr;
#pragma unroll
        for (int p = 0; p < 4; p++) {
            int n = bn + tx * 2 + 32 * p;
            float2 v = unpk2(acc[r][p]);
            if (bias) { v.x += bias[n]; v.y += bias[n + 1]; }
            if (arow) { v.x += arow[n]; v.y += arow[n + 1]; }
            *(float2*)&Z[(size_t)m * N4H + n] = v;
        }
    }
}

// ---------------- LSTM cell (gates + masked state update) ----------------
__global__ void lstm_cell(const float* __restrict__ Z,
                          const int* __restrict__ maskSrc, int maskStride,
                          float* __restrict__ h, float* __restrict__ c)
{
    int i = blockIdx.x * blockDim.x + threadIdx.x;
    if (i >= B_ * H_) return;
    int m = i >> 10;        // H_ = 1024
    int j = i & 1023;

    if (maskSrc[(size_t)m * maskStride] == 0) return;   // frozen row

    const float* zr = Z + (size_t)m * N4H;
    float zi = zr[j], zf = zr[1024 + j], zg = zr[2048 + j], zo = zr[3072 + j];

    float ig = 1.0f / (1.0f + expf(-zi));
    float fg = 1.0f / (1.0f + expf(-zf));
    float gg = tanhf(zg);
    float og = 1.0f / (1.0f + expf(-zo));

    float c2 = fg * c[i] + ig * gg;
    c[i] = c2;
    h[i] = og * tanhf(c2);
}

// ---------------- decoder output: logits + softmax + argmax + token feedback ----------------
// grid: B_/4 blocks of 128 threads; each block handles 4 batch rows.
__global__ void dec_output(const float* __restrict__ h,
                           const float* __restrict__ outW, const float* __restrict__ outb,
                           float* __restrict__ out, int l,
                           int* __restrict__ tok, float* __restrict__ tokOut)
{
    const int ROWS = 4;
    __shared__ float hs[ROWS][H_];
    __shared__ float red[V_];
    __shared__ float smax, ssum;
    __shared__ int   sarg;

    int m0 = blockIdx.x * ROWS;
    int v  = threadIdx.x;   // 0..127

    for (int idx = threadIdx.x; idx < ROWS * H_; idx += blockDim.x) {
        int r = idx >> 10;
        hs[r][idx & 1023] = h[(size_t)(m0 + r) * H_ + (idx & 1023)];
    }
    __syncthreads();

    float acc[ROWS] = {0.f, 0.f, 0.f, 0.f};
#pragma unroll 8
    for (int k = 0; k < H_; k++) {
        float w = outW[(size_t)k * V_ + v];
#pragma unroll
        for (int r = 0; r < ROWS; r++) acc[r] += hs[r][k] * w;
    }
    float bb = outb[v];

    for (int r = 0; r < ROWS; r++) {
        float logit = acc[r] + bb;
        red[v] = logit;
        __syncthreads();
        if (v == 0) {
            float mx = red[0]; int am = 0;
            for (int q = 1; q < V_; q++) if (red[q] > mx) { mx = red[q]; am = q; }
            smax = mx; sarg = am;
        }
        __syncthreads();
        float e = expf(logit - smax);
        red[v] = e;
        __syncthreads();
        if (v == 0) {
            float s = 0.f;
            for (int q = 0; q < V_; q++) s += red[q];
            ssum = s;
        }
        __syncthreads();
        int m = m0 + r;
        out[(size_t)m * (L_ * V_) + (size_t)l * V_ + v] = e / ssum;
        if (v == 0) {
            tok[m] = sarg;
            if (tokOut) tokOut[(size_t)l * B_ + m] = (float)sarg;
        }
        __syncthreads();
    }
}

// ---------------- init ----------------
__global__ void init_state(float* __restrict__ h, float* __restrict__ c, int* __restrict__ tok)
{
    int i = blockIdx.x * blockDim.x + threadIdx.x;
    if (i < B_ * H_) { h[i] = 0.f; c[i] = 0.f; }
    if (i < B_) tok[i] = V_ - 1;   // delimiter = vocab - 1
}

// ---------------- launch ----------------
extern "C" void kernel_launch(void* const* d_in, const int* in_sizes, int n_in,
                              void* d_out, int out_size)
{
    // Input order (metadata): inputs, [max_len], enc_emb, enc_W, enc_U, enc_b,
    //                         dec_emb, dec_W, dec_U, dec_b, out_W, out_b
    int base = 1;
    if (n_in >= 12 && in_sizes[1] == 1) base = 2;   // max_len present as scalar

    const int*   inputs  = (const int*)  d_in[0];
    const float* enc_emb = (const float*)d_in[base + 0];
    const float* enc_W   = (const float*)d_in[base + 1];
    const float* enc_U   = (const float*)d_in[base + 2];
    const float* enc_b   = (const float*)d_in[base + 3];
    const float* dec_emb = (const float*)d_in[base + 4];
    const float* dec_W   = (const float*)d_in[base + 5];
    const float* dec_U   = (const float*)d_in[base + 6];
    const float* dec_b   = (const float*)d_in[base + 7];
    const float* out_W   = (const float*)d_in[base + 8];
    const float* out_b   = (const float*)d_in[base + 9];
    float* out = (float*)d_out;

    float *p_h, *p_c, *p_z, *p_decEW;
    int* p_tok;
    cudaGetSymbolAddress((void**)&p_h, g_h);
    cudaGetSymbolAddress((void**)&p_c, g_c);
    cudaGetSymbolAddress((void**)&p_z, g_z);
    cudaGetSymbolAddress((void**)&p_decEW, g_decEW);
    cudaGetSymbolAddress((void**)&p_tok, g_tok);

    float* tokOut = nullptr;
    if (out_size >= B_ * L_ * V_ + L_ * B_) tokOut = out + (size_t)B_ * L_ * V_;

    // init state
    init_state<<<(B_ * H_ + 255) / 256, 256>>>(p_h, p_c, p_tok);

    // one-time: dec_emb @ dec_W  (M = V_ = 128)
    {
        dim3 g(N4H / BN, V_ / BM);
        lstm_gemm<<<g, 256>>>(nullptr, nullptr,
                              dec_emb, dec_W,
                              nullptr, 0,
                              nullptr, nullptr,
                              nullptr, p_decEW);
    }

    dim3 gstep(N4H / BN, B_ / BM);   // 32 x 4 = 128 CTAs

    // ---- encoder ----
    for (int t = 0; t < T_; t++) {
        lstm_gemm<<<gstep, 256>>>(p_h, enc_U,
                                  enc_emb, enc_W,
                                  inputs + t, T_,
                                  nullptr, nullptr,
                                  enc_b, p_z);
        lstm_cell<<<(B_ * H_ + 255) / 256, 256>>>(p_z, inputs + t, T_, p_h, p_c);
    }

    // ---- decoder ----
    for (int l = 0; l < L_; l++) {
        lstm_gemm<<<gstep, 256>>>(p_h, dec_U,
                                  nullptr, nullptr,
                                  nullptr, 0,
                                  p_decEW, p_tok,
                                  dec_b, p_z);
        lstm_cell<<<(B_ * H_ + 255) / 256, 256>>>(p_z, p_tok, 1, p_h, p_c);
        dec_output<<<B_ / 4, V_>>>(p_h, out_W, out_b, out, l, p_tok, tokOut);
    }
}